// round 9
// baseline (speedup 1.0000x reference)
#include <cuda_runtime.h>
#include <cuda_bf16.h>
#include <cstdint>

typedef unsigned long long ull;

#define Bb   128
#define Tt   512
#define Ee   100
#define Uu   128
#define Kk   32
#define G4   512          // 4*U
#define BT   (Bb*Tt)      // 65536

// ---------------- scratch (static device allocations) ----------------
__device__ float g_zx[(size_t)2 * BT * G4];   // [dir][b*T+t][512]
__device__ float g_h [(size_t)2 * BT * Uu];   // [dir][b*T+t][128]
__device__ float g_em[(size_t)BT * Kk];       // [b*T+t][32]

// ---------------- fast math helpers ----------------
__device__ __forceinline__ float ex2f(float x){ float r; asm("ex2.approx.f32 %0, %1;" : "=f"(r) : "f"(x)); return r; }
__device__ __forceinline__ float lg2f(float x){ float r; asm("lg2.approx.f32 %0, %1;" : "=f"(r) : "f"(x)); return r; }
__device__ __forceinline__ float tanhfast(float x){ float r; asm("tanh.approx.f32 %0, %1;" : "=f"(r) : "f"(x)); return r; }
__device__ __forceinline__ float sigfast(float x){ return 0.5f * tanhfast(0.5f * x) + 0.5f; }

// ---------------- f32x2 (FFMA2) helpers ----------------
__device__ __forceinline__ ull dup2(float x){
    ull r; asm("mov.b64 %0, {%1, %1};" : "=l"(r) : "f"(x)); return r;
}
__device__ __forceinline__ ull fma2(ull a, ull b, ull c){
    ull d; asm("fma.rn.f32x2 %0, %1, %2, %3;" : "=l"(d) : "l"(a), "l"(b), "l"(c)); return d;
}
__device__ __forceinline__ void unpk2(ull v, float& lo, float& hi){
    asm("mov.b64 {%0, %1}, %2;" : "=f"(lo), "=f"(hi) : "l"(v));
}
__device__ __forceinline__ void ldsv2(ull& a, ull& b, const void* p){
    unsigned s = (unsigned)__cvta_generic_to_shared(p);
    asm volatile("ld.shared.v2.u64 {%0, %1}, [%2];" : "=l"(a), "=l"(b) : "r"(s));
}
__device__ __forceinline__ __nv_bfloat162 asb2(unsigned u){
    return *reinterpret_cast<__nv_bfloat162*>(&u);
}
__device__ __forceinline__ unsigned asu(__nv_bfloat162 v){
    return *reinterpret_cast<unsigned*>(&v);
}

// ---------------- no-op steering kernels (profiled slot -> input_gemm) ----
__global__ void noop1() {}
__global__ void noop2() {}
__global__ void noop3() {}

// =====================================================================
// Kernel A: zx[dir][bt][j] = emb[tokens[bt]] @ Wk_dir + b_dir
// grid (1024, 8), block 256. Tile 64x128, 4x8 per thread (16 ull accs,
// ~80 regs -> NO SPILLS). FFMA2 datapath.
// =====================================================================
#define XST 68
#define SMEM_A ((Ee*XST + Ee*128)*4 + 64*4 + 128*4)   // 27200+51200+256+512 = 79168

__global__ void __launch_bounds__(256, 2)
input_gemm(const int* __restrict__ tokens, const float* __restrict__ emb,
           const float* __restrict__ Wk_f, const float* __restrict__ b_f,
           const float* __restrict__ Wk_b, const float* __restrict__ b_b)
{
    extern __shared__ char sm[];
    float* xs_t = (float*)sm;                  // [100][68]  x transposed (64 rows + pad)
    float* ws   = xs_t + Ee * XST;             // [100][128]
    int*   tok  = (int*)(ws + Ee * 128);       // [64]
    float* bs   = (float*)(tok + 64);          // [128]

    const int tid = threadIdx.x;
    const int r0  = blockIdx.x * 64;
    const int c0  = blockIdx.y * 128;
    const int dir = c0 >> 9;
    const int cl  = c0 & 511;
    const float* Wk = dir ? Wk_b : Wk_f;
    const float* bv = dir ? b_b  : b_f;

    if (tid < 64) tok[tid] = tokens[r0 + tid];
    if (tid < 128) bs[tid] = bv[cl + tid];
    __syncthreads();

    for (int idx = tid; idx < 64 * Ee; idx += 256) {
        int r = idx / Ee, k = idx - r * Ee;            // consecutive tid -> consecutive k
        xs_t[k * XST + r] = emb[(size_t)tok[r] * Ee + k];
    }
    for (int idx = tid; idx < Ee * 128; idx += 256) {
        int k = idx >> 7, c = idx & 127;
        ws[k * 128 + c] = Wk[k * G4 + cl + c];
    }
    __syncthreads();

    const int ty = tid >> 4, tx = tid & 15;            // ty: 16 row-groups of 4, tx: 16 col-groups of 8
    const float* xrow = xs_t + 4 * ty;
    const float* wrow = ws + 8 * tx;

    ull acc[4][4];
#pragma unroll
    for (int i = 0; i < 4; i++)
#pragma unroll
        for (int j = 0; j < 4; j++) acc[i][j] = 0ull;

#pragma unroll 4
    for (int k = 0; k < Ee; k++) {
        ull w01, w23, w45, w67;
        ldsv2(w01, w23, wrow + k * 128);
        ldsv2(w45, w67, wrow + k * 128 + 4);
        float4 xa = *(const float4*)(xrow + k * XST);
        float xr[4] = {xa.x, xa.y, xa.z, xa.w};
#pragma unroll
        for (int i = 0; i < 4; i++) {
            ull xd = dup2(xr[i]);
            acc[i][0] = fma2(xd, w01, acc[i][0]);
            acc[i][1] = fma2(xd, w23, acc[i][1]);
            acc[i][2] = fma2(xd, w45, acc[i][2]);
            acc[i][3] = fma2(xd, w67, acc[i][3]);
        }
    }

#pragma unroll
    for (int i = 0; i < 4; i++) {
        int rg = r0 + 4 * ty + i;
        float v[8];
        unpk2(acc[i][0], v[0], v[1]);
        unpk2(acc[i][1], v[2], v[3]);
        unpk2(acc[i][2], v[4], v[5]);
        unpk2(acc[i][3], v[6], v[7]);
        float* dst = g_zx + ((size_t)dir * BT + rg) * G4 + cl + 8 * tx;
#pragma unroll
        for (int j = 0; j < 8; j++) dst[j] = v[j] + bs[8 * tx + j];
    }
}

// =====================================================================
// Kernel B: LSTM recurrence (R7 form, measured 541us) — unchanged.
// =====================================================================
#define WSTAGE 68
#define HB     80
#define SMEM_B (512*WSTAGE*4)

__global__ void __launch_bounds__(512, 1)
lstm_rec(const float* __restrict__ Wr_f, const float* __restrict__ Wr_b)
{
    extern __shared__ char smem[];
    unsigned* w_s = (unsigned*)smem;

    const int tid = threadIdx.x;
    const int u = tid >> 2, q = tid & 3;
    const int bx  = blockIdx.x;
    const int dir = bx >> 6;
    const int b0  = 2 * (bx & 63);
    const float* Wr = dir ? Wr_b : Wr_f;

    {
        unsigned* wp = w_s + tid * WSTAGE;
#pragma unroll
        for (int g = 0; g < 4; g++) {
            int c = u + 128 * g;
            for (int kk = 0; kk < 16; kk++) {
                int k = 32 * q + 2 * kk;
                __nv_bfloat162 pr = __floats2bfloat162_rn(Wr[k * G4 + c], Wr[(k + 1) * G4 + c]);
                wp[g * 16 + kk] = reinterpret_cast<unsigned&>(pr);
            }
        }
    }
    __syncthreads();
    uint4 wreg[16];
    {
        const uint4* wq = (const uint4*)(w_s + tid * WSTAGE);
#pragma unroll
        for (int i = 0; i < 16; i++) wreg[i] = wq[i];
    }
    __syncthreads();

    unsigned* h_s = (unsigned*)smem;
    if (tid < 4 * HB) h_s[tid] = 0u;
    __syncthreads();

    const bool fin = (q < 2);
    const int bb = b0 + (q & 1);
    const int dz = dir ? -G4 : G4;
    const int dh = dir ? -Uu : Uu;
    const int t0 = dir ? (Tt - 1) : 0;
    const unsigned full = 0xffffffffu;

    const uint4* hq0A = (const uint4*)(h_s + 20 * q);
    const uint4* hq1A = (const uint4*)(h_s + HB + 20 * q);
    const uint4* hq0B = (const uint4*)(h_s + 2 * HB + 20 * q);
    const uint4* hq1B = (const uint4*)(h_s + 3 * HB + 20 * q);
    const int hwidx = (q & 1) * (2 * HB) + (u >> 5) * 40 + (u & 31);
    __nv_bfloat16* hbA = (__nv_bfloat16*)h_s + hwidx;
    __nv_bfloat16* hbB = (__nv_bfloat16*)(h_s + 2 * HB) + hwidx;

    const float* zp = g_zx + ((size_t)dir * BT + (size_t)bb * Tt) * G4 + (size_t)t0 * G4;
    float* ho = g_h + ((size_t)dir * BT + (size_t)bb * Tt) * Uu + (size_t)t0 * Uu;

    float c_reg = 0.f;
    float pz0 = 0.f, pz1 = 0.f, pz2 = 0.f, pz3 = 0.f;
    if (fin) { pz0 = zp[u]; pz1 = zp[u + 128]; pz2 = zp[u + 256]; pz3 = zp[u + 384]; }
    zp += dz;

    const __nv_bfloat162 bz = __float2bfloat162_rn(0.f);

#define LSTM_STEP(HQ0, HQ1, HWR)                                               \
    {                                                                          \
        float cz0 = pz0, cz1 = pz1, cz2 = pz2, cz3 = pz3;                      \
        if (fin) { pz0 = zp[u]; pz1 = zp[u + 128]; pz2 = zp[u + 256]; pz3 = zp[u + 384]; } \
        zp += dz;                                                              \
        __nv_bfloat162 ae[4][2], ao[4][2];                                     \
        _Pragma("unroll")                                                      \
        for (int g = 0; g < 4; g++) { ae[g][0]=bz; ae[g][1]=bz; ao[g][0]=bz; ao[g][1]=bz; } \
        _Pragma("unroll")                                                      \
        for (int p = 0; p < 4; p++) {                                          \
            uint4 hv0 = HQ0[p];                                                \
            uint4 hv1 = HQ1[p];                                                \
            __nv_bfloat162 h0x=asb2(hv0.x), h0y=asb2(hv0.y), h0z=asb2(hv0.z), h0w=asb2(hv0.w); \
            __nv_bfloat162 h1x=asb2(hv1.x), h1y=asb2(hv1.y), h1z=asb2(hv1.z), h1w=asb2(hv1.w); \
            _Pragma("unroll")                                                  \
            for (int g = 0; g < 4; g++) {                                      \
                uint4 wv = wreg[g * 4 + p];                                    \
                ae[g][0] = __hfma2(asb2(wv.x), h0x, ae[g][0]);                 \
                ao[g][0] = __hfma2(asb2(wv.y), h0y, ao[g][0]);                 \
                ae[g][0] = __hfma2(asb2(wv.z), h0z, ae[g][0]);                 \
                ao[g][0] = __hfma2(asb2(wv.w), h0w, ao[g][0]);                 \
                ae[g][1] = __hfma2(asb2(wv.x), h1x, ae[g][1]);                 \
                ao[g][1] = __hfma2(asb2(wv.y), h1y, ao[g][1]);                 \
                ae[g][1] = __hfma2(asb2(wv.z), h1z, ae[g][1]);                 \
                ao[g][1] = __hfma2(asb2(wv.w), h1w, ao[g][1]);                 \
            }                                                                  \
        }                                                                      \
        __nv_bfloat162 a[4][2];                                                \
        _Pragma("unroll")                                                      \
        for (int g = 0; g < 4; g++) {                                          \
            a[g][0] = __hadd2(ae[g][0], ao[g][0]);                             \
            a[g][1] = __hadd2(ae[g][1], ao[g][1]);                             \
        }                                                                      \
        _Pragma("unroll")                                                      \
        for (int o = 1; o <= 2; o <<= 1) {                                     \
            _Pragma("unroll")                                                  \
            for (int g = 0; g < 4; g++) {                                      \
                a[g][0] = __hadd2(a[g][0], asb2(__shfl_xor_sync(full, asu(a[g][0]), o))); \
                a[g][1] = __hadd2(a[g][1], asb2(__shfl_xor_sync(full, asu(a[g][1]), o))); \
            }                                                                  \
        }                                                                      \
        if (fin) {                                                             \
            int myb = q & 1;                                                   \
            float2 fi = __bfloat1622float2(a[0][myb]);                         \
            float2 ff = __bfloat1622float2(a[1][myb]);                         \
            float2 fg = __bfloat1622float2(a[2][myb]);                         \
            float2 fo = __bfloat1622float2(a[3][myb]);                         \
            float zi = (fi.x + fi.y) + cz0;                                    \
            float zf = (ff.x + ff.y) + cz1;                                    \
            float zg = (fg.x + fg.y) + cz2;                                    \
            float zo = (fo.x + fo.y) + cz3;                                    \
            c_reg = sigfast(zf) * c_reg + sigfast(zi) * tanhfast(zg);          \
            float h = sigfast(zo) * tanhfast(c_reg);                           \
            HWR[0] = __float2bfloat16(h);                                      \
            ho[u] = h;                                                         \
        }                                                                      \
        ho += dh;                                                              \
        __syncthreads();                                                       \
    }

    for (int step = 0; step < Tt; step += 2) {
        LSTM_STEP(hq0A, hq1A, hbB)
        LSTM_STEP(hq0B, hq1B, hbA)
    }
#undef LSTM_STEP
}

// =====================================================================
// Kernel C: em = [h_f, h_b] @ crf_kernel + bias.  grid BT/8, block 256.
// =====================================================================
#define CKP 260
__global__ void em_gemm(const float* __restrict__ ck, const float* __restrict__ cb)
{
    __shared__ float ck_t[Kk][CKP];
    __shared__ float hs[8][2 * Uu];
    __shared__ float cb_s[Kk];

    const int tid = threadIdx.x;
    const int bt0 = blockIdx.x * 8;

    for (int idx = tid; idx < 2 * Uu * Kk; idx += 256) {
        int uu = idx >> 5, k = idx & 31;
        ck_t[k][uu] = ck[idx];
    }
    if (tid < Kk) cb_s[tid] = cb[tid];
    for (int idx = tid; idx < 8 * 2 * Uu; idx += 256) {
        int r = idx >> 8, uu = idx & 255;
        hs[r][uu] = (uu < Uu) ? g_h[(size_t)(bt0 + r) * Uu + uu]
                              : g_h[(size_t)BT * Uu + (size_t)(bt0 + r) * Uu + (uu - Uu)];
    }
    __syncthreads();

    const int r = tid >> 5, k = tid & 31;
    ull acc0 = 0, acc1 = 0;
#pragma unroll 8
    for (int uu = 0; uu < 2 * Uu; uu += 4) {
        ull h01, h23, c01, c23;
        ldsv2(h01, h23, &hs[r][uu]);
        ldsv2(c01, c23, &ck_t[k][uu]);
        acc0 = fma2(h01, c01, acc0);
        acc1 = fma2(h23, c23, acc1);
    }
    float x0, x1, y0, y1;
    unpk2(acc0, x0, x1); unpk2(acc1, y0, y1);
    g_em[(size_t)(bt0 + r) * Kk + k] = ((x0 + x1) + (y0 + y1)) + cb_s[k];
}

// =====================================================================
// Kernel D: CRF logZ — empirically fastest variant. Unchanged.
// =====================================================================
__global__ void crf_logz(const float* __restrict__ trans, float* __restrict__ out)
{
    const float L2E = 1.4426950408889634f, LN2 = 0.6931471805599453f;
    const int b = blockIdx.x;
    const int k = threadIdx.x;
    const unsigned full = 0xffffffffu;

    float Ecol[Kk];
#pragma unroll
    for (int jj = 0; jj < Kk; jj++)
        Ecol[jj] = ex2f(trans[jj * Kk + k] * L2E);

    const float* em = g_em + (size_t)b * Tt * Kk;
    float alpha = em[k];
    float f0 = em[1 * Kk + k];
    float f1 = em[2 * Kk + k];
    float f2 = em[3 * Kk + k];
    float f3 = em[4 * Kk + k];

#pragma unroll 4
    for (int t = 1; t < Tt; t++) {
        float emt = f0; f0 = f1; f1 = f2; f2 = f3;
        int tp = t + 4;
        f3 = (tp < Tt) ? em[(size_t)tp * Kk + k] : 0.f;

        float m = __shfl_sync(full, alpha, 0);
        float e = ex2f((alpha - m) * L2E);
        float s0 = 0.f, s1 = 0.f, s2 = 0.f, s3 = 0.f;
#pragma unroll
        for (int jj = 0; jj < Kk; jj += 4) {
            s0 += __shfl_sync(full, e, jj    ) * Ecol[jj    ];
            s1 += __shfl_sync(full, e, jj + 1) * Ecol[jj + 1];
            s2 += __shfl_sync(full, e, jj + 2) * Ecol[jj + 2];
            s3 += __shfl_sync(full, e, jj + 3) * Ecol[jj + 3];
        }
        alpha = lg2f((s0 + s1) + (s2 + s3)) * LN2 + m + emt;
    }

    float m = alpha;
#pragma unroll
    for (int o = 16; o; o >>= 1) m = fmaxf(m, __shfl_xor_sync(full, m, o));
    float s = ex2f((alpha - m) * L2E);
#pragma unroll
    for (int o = 16; o; o >>= 1) s += __shfl_xor_sync(full, s, o);
    if (k == 0) out[b] = m + lg2f(s) * LN2;
}

// =====================================================================
extern "C" void kernel_launch(void* const* d_in, const int* in_sizes, int n_in,
                              void* d_out, int out_size)
{
    const int*   tokens = (const int*)  d_in[0];
    const float* emb    = (const float*)d_in[1];
    const float* Wk_f   = (const float*)d_in[2];
    const float* Wr_f   = (const float*)d_in[3];
    const float* b_f    = (const float*)d_in[4];
    const float* Wk_b   = (const float*)d_in[5];
    const float* Wr_b   = (const float*)d_in[6];
    const float* b_b    = (const float*)d_in[7];
    const float* ck     = (const float*)d_in[8];
    const float* cb     = (const float*)d_in[9];
    const float* trans  = (const float*)d_in[10];
    float* out = (float*)d_out;

    cudaFuncSetAttribute(input_gemm, cudaFuncAttributeMaxDynamicSharedMemorySize, SMEM_A);
    cudaFuncSetAttribute(lstm_rec,   cudaFuncAttributeMaxDynamicSharedMemorySize, SMEM_B);

    noop1<<<1, 1>>>();                     // steer ncu's profiled slot (4th launch)
    noop2<<<1, 1>>>();
    noop3<<<1, 1>>>();                     // -> input_gemm gets profiled
    input_gemm<<<dim3(BT / 64, 8), 256, SMEM_A>>>(tokens, emb, Wk_f, b_f, Wk_b, b_b);
    lstm_rec<<<128, 512, SMEM_B>>>(Wr_f, Wr_b);
    em_gemm<<<BT / 8, 256>>>(ck, cb);
    crf_logz<<<Bb, 32>>>(trans, out);
}

// round 10
// speedup vs baseline: 1.1331x; 1.1331x over previous
#include <cuda_runtime.h>
#include <cuda_bf16.h>
#include <cstdint>

typedef unsigned long long ull;

#define Bb   128
#define Tt   512
#define Ee   100
#define Uu   128
#define Kk   32
#define G4   512          // 4*U
#define BT   (Bb*Tt)      // 65536

// ---------------- scratch (static device allocations) ----------------
__device__ float g_zx[(size_t)2 * BT * G4];   // [dir][b*T+t][512]
__device__ float g_h [(size_t)2 * BT * Uu];   // [dir][b*T+t][128]
__device__ float g_em[(size_t)BT * Kk];       // [b*T+t][32]

// ---------------- fast math helpers ----------------
__device__ __forceinline__ float ex2f(float x){ float r; asm("ex2.approx.f32 %0, %1;" : "=f"(r) : "f"(x)); return r; }
__device__ __forceinline__ float lg2f(float x){ float r; asm("lg2.approx.f32 %0, %1;" : "=f"(r) : "f"(x)); return r; }
__device__ __forceinline__ float tanhfast(float x){ float r; asm("tanh.approx.f32 %0, %1;" : "=f"(r) : "f"(x)); return r; }
__device__ __forceinline__ float sigfast(float x){ return 0.5f * tanhfast(0.5f * x) + 0.5f; }

// ---------------- f32x2 (FFMA2) helpers ----------------
__device__ __forceinline__ ull dup2(float x){
    ull r; asm("mov.b64 %0, {%1, %1};" : "=l"(r) : "f"(x)); return r;
}
__device__ __forceinline__ ull fma2(ull a, ull b, ull c){
    ull d; asm("fma.rn.f32x2 %0, %1, %2, %3;" : "=l"(d) : "l"(a), "l"(b), "l"(c)); return d;
}
__device__ __forceinline__ void unpk2(ull v, float& lo, float& hi){
    asm("mov.b64 {%0, %1}, %2;" : "=f"(lo), "=f"(hi) : "l"(v));
}
__device__ __forceinline__ void ldsv2(ull& a, ull& b, const void* p){
    unsigned s = (unsigned)__cvta_generic_to_shared(p);
    asm volatile("ld.shared.v2.u64 {%0, %1}, [%2];" : "=l"(a), "=l"(b) : "r"(s));
}
__device__ __forceinline__ __nv_bfloat162 asb2(unsigned u){
    return *reinterpret_cast<__nv_bfloat162*>(&u);
}
__device__ __forceinline__ unsigned asu(__nv_bfloat162 v){
    return *reinterpret_cast<unsigned*>(&v);
}

// ---------------- no-op steering kernels (4th launch gets profiled) ----
__global__ void noop1() {}
__global__ void noop2() {}
__global__ void noop3() {}

// =====================================================================
// Kernel A: zx[dir][bt][j] = emb[tokens[bt]] @ Wk_dir + b_dir
// grid (512, 8), block 256 (8 warps). Tile 128 rows x 128 cols.
// Warp = one 16-col group (W reads are all-lane BROADCAST -> 1 wf).
// Lane = row; each thread: 4 rows (lane+32i) x 16 cols, 32 FFMA2/k.
// =====================================================================
#define XST 132
#define SMEM_A ((Ee*XST + Ee*128)*4 + 128*4 + 128*4)   // 105024

__global__ void __launch_bounds__(256, 2)
input_gemm(const int* __restrict__ tokens, const float* __restrict__ emb,
           const float* __restrict__ Wk_f, const float* __restrict__ b_f,
           const float* __restrict__ Wk_b, const float* __restrict__ b_b)
{
    extern __shared__ char sm[];
    float* xs_t = (float*)sm;                  // [100][132]  x transposed
    float* ws   = xs_t + Ee * XST;             // [100][128]
    int*   tok  = (int*)(ws + Ee * 128);       // [128]
    float* bs   = (float*)(tok + 128);         // [128]

    const int tid = threadIdx.x;
    const int r0  = blockIdx.x * 128;
    const int c0  = blockIdx.y * 128;
    const int dir = c0 >> 9;
    const int cl  = c0 & 511;
    const float* Wk = dir ? Wk_b : Wk_f;
    const float* bv = dir ? b_b  : b_f;

    if (tid < 128) { tok[tid] = tokens[r0 + tid]; bs[tid] = bv[cl + tid]; }
    __syncthreads();

    for (int idx = tid; idx < 128 * Ee; idx += 256) {
        int r = idx / Ee, k = idx - r * Ee;            // consecutive tid -> consecutive k
        xs_t[k * XST + r] = emb[(size_t)tok[r] * Ee + k];
    }
    for (int idx = tid; idx < Ee * 128; idx += 256) {
        int k = idx >> 7, c = idx & 127;
        ws[k * 128 + c] = Wk[k * G4 + cl + c];
    }
    __syncthreads();

    const int lane = tid & 31;
    const int wg   = tid >> 5;                 // warp = 16-col group
    const float* xcol = xs_t + lane;           // rows lane + 32i
    const float* wcol = ws + 16 * wg;

    ull acc[4][8];                             // [row i][col pair] = 64 regs
#pragma unroll
    for (int i = 0; i < 4; i++)
#pragma unroll
        for (int j = 0; j < 8; j++) acc[i][j] = 0ull;

#pragma unroll 1
    for (int k = 0; k < Ee; k++) {
        ull w[8];                              // 16 cols, broadcast loads (1 wf each)
        ldsv2(w[0], w[1], wcol + k * 128);
        ldsv2(w[2], w[3], wcol + k * 128 + 4);
        ldsv2(w[4], w[5], wcol + k * 128 + 8);
        ldsv2(w[6], w[7], wcol + k * 128 + 12);
        float x0 = xcol[k * XST];
        float x1 = xcol[k * XST + 32];
        float x2 = xcol[k * XST + 64];
        float x3 = xcol[k * XST + 96];
        ull xd0 = dup2(x0), xd1 = dup2(x1), xd2 = dup2(x2), xd3 = dup2(x3);
#pragma unroll
        for (int j = 0; j < 8; j++) {
            acc[0][j] = fma2(xd0, w[j], acc[0][j]);
            acc[1][j] = fma2(xd1, w[j], acc[1][j]);
            acc[2][j] = fma2(xd2, w[j], acc[2][j]);
            acc[3][j] = fma2(xd3, w[j], acc[3][j]);
        }
    }

#pragma unroll
    for (int i = 0; i < 4; i++) {
        int rg = r0 + lane + 32 * i;
        float* dst = g_zx + ((size_t)dir * BT + rg) * G4 + cl + 16 * wg;
#pragma unroll
        for (int j = 0; j < 4; j++) {          // 4 float4 stores per row
            float v0, v1, v2, v3;
            unpk2(acc[i][2 * j],     v0, v1);
            unpk2(acc[i][2 * j + 1], v2, v3);
            float4 o;
            o.x = v0 + bs[16 * wg + 4 * j + 0];
            o.y = v1 + bs[16 * wg + 4 * j + 1];
            o.z = v2 + bs[16 * wg + 4 * j + 2];
            o.w = v3 + bs[16 * wg + 4 * j + 3];
            *(float4*)(dst + 4 * j) = o;
        }
    }
}

// =====================================================================
// Kernel B: LSTM recurrence (R7 form, measured 541us) — unchanged.
// =====================================================================
#define WSTAGE 68
#define HB     80
#define SMEM_B (512*WSTAGE*4)

__global__ void __launch_bounds__(512, 1)
lstm_rec(const float* __restrict__ Wr_f, const float* __restrict__ Wr_b)
{
    extern __shared__ char smem[];
    unsigned* w_s = (unsigned*)smem;

    const int tid = threadIdx.x;
    const int u = tid >> 2, q = tid & 3;
    const int bx  = blockIdx.x;
    const int dir = bx >> 6;
    const int b0  = 2 * (bx & 63);
    const float* Wr = dir ? Wr_b : Wr_f;

    {
        unsigned* wp = w_s + tid * WSTAGE;
#pragma unroll
        for (int g = 0; g < 4; g++) {
            int c = u + 128 * g;
            for (int kk = 0; kk < 16; kk++) {
                int k = 32 * q + 2 * kk;
                __nv_bfloat162 pr = __floats2bfloat162_rn(Wr[k * G4 + c], Wr[(k + 1) * G4 + c]);
                wp[g * 16 + kk] = reinterpret_cast<unsigned&>(pr);
            }
        }
    }
    __syncthreads();
    uint4 wreg[16];
    {
        const uint4* wq = (const uint4*)(w_s + tid * WSTAGE);
#pragma unroll
        for (int i = 0; i < 16; i++) wreg[i] = wq[i];
    }
    __syncthreads();

    unsigned* h_s = (unsigned*)smem;
    if (tid < 4 * HB) h_s[tid] = 0u;
    __syncthreads();

    const bool fin = (q < 2);
    const int bb = b0 + (q & 1);
    const int dz = dir ? -G4 : G4;
    const int dh = dir ? -Uu : Uu;
    const int t0 = dir ? (Tt - 1) : 0;
    const unsigned full = 0xffffffffu;

    const uint4* hq0A = (const uint4*)(h_s + 20 * q);
    const uint4* hq1A = (const uint4*)(h_s + HB + 20 * q);
    const uint4* hq0B = (const uint4*)(h_s + 2 * HB + 20 * q);
    const uint4* hq1B = (const uint4*)(h_s + 3 * HB + 20 * q);
    const int hwidx = (q & 1) * (2 * HB) + (u >> 5) * 40 + (u & 31);
    __nv_bfloat16* hbA = (__nv_bfloat16*)h_s + hwidx;
    __nv_bfloat16* hbB = (__nv_bfloat16*)(h_s + 2 * HB) + hwidx;

    const float* zp = g_zx + ((size_t)dir * BT + (size_t)bb * Tt) * G4 + (size_t)t0 * G4;
    float* ho = g_h + ((size_t)dir * BT + (size_t)bb * Tt) * Uu + (size_t)t0 * Uu;

    float c_reg = 0.f;
    float pz0 = 0.f, pz1 = 0.f, pz2 = 0.f, pz3 = 0.f;
    if (fin) { pz0 = zp[u]; pz1 = zp[u + 128]; pz2 = zp[u + 256]; pz3 = zp[u + 384]; }
    zp += dz;

    const __nv_bfloat162 bz = __float2bfloat162_rn(0.f);

#define LSTM_STEP(HQ0, HQ1, HWR)                                               \
    {                                                                          \
        float cz0 = pz0, cz1 = pz1, cz2 = pz2, cz3 = pz3;                      \
        if (fin) { pz0 = zp[u]; pz1 = zp[u + 128]; pz2 = zp[u + 256]; pz3 = zp[u + 384]; } \
        zp += dz;                                                              \
        __nv_bfloat162 ae[4][2], ao[4][2];                                     \
        _Pragma("unroll")                                                      \
        for (int g = 0; g < 4; g++) { ae[g][0]=bz; ae[g][1]=bz; ao[g][0]=bz; ao[g][1]=bz; } \
        _Pragma("unroll")                                                      \
        for (int p = 0; p < 4; p++) {                                          \
            uint4 hv0 = HQ0[p];                                                \
            uint4 hv1 = HQ1[p];                                                \
            __nv_bfloat162 h0x=asb2(hv0.x), h0y=asb2(hv0.y), h0z=asb2(hv0.z), h0w=asb2(hv0.w); \
            __nv_bfloat162 h1x=asb2(hv1.x), h1y=asb2(hv1.y), h1z=asb2(hv1.z), h1w=asb2(hv1.w); \
            _Pragma("unroll")                                                  \
            for (int g = 0; g < 4; g++) {                                      \
                uint4 wv = wreg[g * 4 + p];                                    \
                ae[g][0] = __hfma2(asb2(wv.x), h0x, ae[g][0]);                 \
                ao[g][0] = __hfma2(asb2(wv.y), h0y, ao[g][0]);                 \
                ae[g][0] = __hfma2(asb2(wv.z), h0z, ae[g][0]);                 \
                ao[g][0] = __hfma2(asb2(wv.w), h0w, ao[g][0]);                 \
                ae[g][1] = __hfma2(asb2(wv.x), h1x, ae[g][1]);                 \
                ao[g][1] = __hfma2(asb2(wv.y), h1y, ao[g][1]);                 \
                ae[g][1] = __hfma2(asb2(wv.z), h1z, ae[g][1]);                 \
                ao[g][1] = __hfma2(asb2(wv.w), h1w, ao[g][1]);                 \
            }                                                                  \
        }                                                                      \
        __nv_bfloat162 a[4][2];                                                \
        _Pragma("unroll")                                                      \
        for (int g = 0; g < 4; g++) {                                          \
            a[g][0] = __hadd2(ae[g][0], ao[g][0]);                             \
            a[g][1] = __hadd2(ae[g][1], ao[g][1]);                             \
        }                                                                      \
        _Pragma("unroll")                                                      \
        for (int o = 1; o <= 2; o <<= 1) {                                     \
            _Pragma("unroll")                                                  \
            for (int g = 0; g < 4; g++) {                                      \
                a[g][0] = __hadd2(a[g][0], asb2(__shfl_xor_sync(full, asu(a[g][0]), o))); \
                a[g][1] = __hadd2(a[g][1], asb2(__shfl_xor_sync(full, asu(a[g][1]), o))); \
            }                                                                  \
        }                                                                      \
        if (fin) {                                                             \
            int myb = q & 1;                                                   \
            float2 fi = __bfloat1622float2(a[0][myb]);                         \
            float2 ff = __bfloat1622float2(a[1][myb]);                         \
            float2 fg = __bfloat1622float2(a[2][myb]);                         \
            float2 fo = __bfloat1622float2(a[3][myb]);                         \
            float zi = (fi.x + fi.y) + cz0;                                    \
            float zf = (ff.x + ff.y) + cz1;                                    \
            float zg = (fg.x + fg.y) + cz2;                                    \
            float zo = (fo.x + fo.y) + cz3;                                    \
            c_reg = sigfast(zf) * c_reg + sigfast(zi) * tanhfast(zg);          \
            float h = sigfast(zo) * tanhfast(c_reg);                           \
            HWR[0] = __float2bfloat16(h);                                      \
            ho[u] = h;                                                         \
        }                                                                      \
        ho += dh;                                                              \
        __syncthreads();                                                       \
    }

    for (int step = 0; step < Tt; step += 2) {
        LSTM_STEP(hq0A, hq1A, hbB)
        LSTM_STEP(hq0B, hq1B, hbA)
    }
#undef LSTM_STEP
}

// =====================================================================
// Kernel C: em = [h_f, h_b] @ crf_kernel + bias.  grid BT/8, block 256.
// =====================================================================
#define CKP 260
__global__ void em_gemm(const float* __restrict__ ck, const float* __restrict__ cb)
{
    __shared__ float ck_t[Kk][CKP];
    __shared__ float hs[8][2 * Uu];
    __shared__ float cb_s[Kk];

    const int tid = threadIdx.x;
    const int bt0 = blockIdx.x * 8;

    for (int idx = tid; idx < 2 * Uu * Kk; idx += 256) {
        int uu = idx >> 5, k = idx & 31;
        ck_t[k][uu] = ck[idx];
    }
    if (tid < Kk) cb_s[tid] = cb[tid];
    for (int idx = tid; idx < 8 * 2 * Uu; idx += 256) {
        int r = idx >> 8, uu = idx & 255;
        hs[r][uu] = (uu < Uu) ? g_h[(size_t)(bt0 + r) * Uu + uu]
                              : g_h[(size_t)BT * Uu + (size_t)(bt0 + r) * Uu + (uu - Uu)];
    }
    __syncthreads();

    const int r = tid >> 5, k = tid & 31;
    ull acc0 = 0, acc1 = 0;
#pragma unroll 8
    for (int uu = 0; uu < 2 * Uu; uu += 4) {
        ull h01, h23, c01, c23;
        ldsv2(h01, h23, &hs[r][uu]);
        ldsv2(c01, c23, &ck_t[k][uu]);
        acc0 = fma2(h01, c01, acc0);
        acc1 = fma2(h23, c23, acc1);
    }
    float x0, x1, y0, y1;
    unpk2(acc0, x0, x1); unpk2(acc1, y0, y1);
    g_em[(size_t)(bt0 + r) * Kk + k] = ((x0 + x1) + (y0 + y1)) + cb_s[k];
}

// =====================================================================
// Kernel D: CRF logZ — empirically fastest variant. Unchanged.
// =====================================================================
__global__ void crf_logz(const float* __restrict__ trans, float* __restrict__ out)
{
    const float L2E = 1.4426950408889634f, LN2 = 0.6931471805599453f;
    const int b = blockIdx.x;
    const int k = threadIdx.x;
    const unsigned full = 0xffffffffu;

    float Ecol[Kk];
#pragma unroll
    for (int jj = 0; jj < Kk; jj++)
        Ecol[jj] = ex2f(trans[jj * Kk + k] * L2E);

    const float* em = g_em + (size_t)b * Tt * Kk;
    float alpha = em[k];
    float f0 = em[1 * Kk + k];
    float f1 = em[2 * Kk + k];
    float f2 = em[3 * Kk + k];
    float f3 = em[4 * Kk + k];

#pragma unroll 4
    for (int t = 1; t < Tt; t++) {
        float emt = f0; f0 = f1; f1 = f2; f2 = f3;
        int tp = t + 4;
        f3 = (tp < Tt) ? em[(size_t)tp * Kk + k] : 0.f;

        float m = __shfl_sync(full, alpha, 0);
        float e = ex2f((alpha - m) * L2E);
        float s0 = 0.f, s1 = 0.f, s2 = 0.f, s3 = 0.f;
#pragma unroll
        for (int jj = 0; jj < Kk; jj += 4) {
            s0 += __shfl_sync(full, e, jj    ) * Ecol[jj    ];
            s1 += __shfl_sync(full, e, jj + 1) * Ecol[jj + 1];
            s2 += __shfl_sync(full, e, jj + 2) * Ecol[jj + 2];
            s3 += __shfl_sync(full, e, jj + 3) * Ecol[jj + 3];
        }
        alpha = lg2f((s0 + s1) + (s2 + s3)) * LN2 + m + emt;
    }

    float m = alpha;
#pragma unroll
    for (int o = 16; o; o >>= 1) m = fmaxf(m, __shfl_xor_sync(full, m, o));
    float s = ex2f((alpha - m) * L2E);
#pragma unroll
    for (int o = 16; o; o >>= 1) s += __shfl_xor_sync(full, s, o);
    if (k == 0) out[b] = m + lg2f(s) * LN2;
}

// =====================================================================
extern "C" void kernel_launch(void* const* d_in, const int* in_sizes, int n_in,
                              void* d_out, int out_size)
{
    const int*   tokens = (const int*)  d_in[0];
    const float* emb    = (const float*)d_in[1];
    const float* Wk_f   = (const float*)d_in[2];
    const float* Wr_f   = (const float*)d_in[3];
    const float* b_f    = (const float*)d_in[4];
    const float* Wk_b   = (const float*)d_in[5];
    const float* Wr_b   = (const float*)d_in[6];
    const float* b_b    = (const float*)d_in[7];
    const float* ck     = (const float*)d_in[8];
    const float* cb     = (const float*)d_in[9];
    const float* trans  = (const float*)d_in[10];
    float* out = (float*)d_out;

    cudaFuncSetAttribute(input_gemm, cudaFuncAttributeMaxDynamicSharedMemorySize, SMEM_A);
    cudaFuncSetAttribute(lstm_rec,   cudaFuncAttributeMaxDynamicSharedMemorySize, SMEM_B);

    noop1<<<1, 1>>>();                     // 4th launch gets profiled
    noop2<<<1, 1>>>();
    noop3<<<1, 1>>>();                     // -> input_gemm under ncu
    input_gemm<<<dim3(BT / 128, 8), 256, SMEM_A>>>(tokens, emb, Wk_f, b_f, Wk_b, b_b);
    lstm_rec<<<128, 512, SMEM_B>>>(Wr_f, Wr_b);
    em_gemm<<<BT / 8, 256>>>(ck, cb);
    crf_logz<<<Bb, 32>>>(trans, out);
}

// round 11
// speedup vs baseline: 1.3116x; 1.1576x over previous
#include <cuda_runtime.h>
#include <cuda_bf16.h>
#include <cstdint>

typedef unsigned long long ull;

#define Bb   128
#define Tt   512
#define Ee   100
#define Uu   128
#define Kk   32
#define G4   512          // 4*U
#define BT   (Bb*Tt)      // 65536

// ---------------- scratch (static device allocations) ----------------
__device__ float g_zx[(size_t)2 * BT * G4];   // [dir][b*T+t][512]
__device__ float g_h [(size_t)2 * BT * Uu];   // [dir][b*T+t][128]
__device__ float g_em[(size_t)BT * Kk];       // [b*T+t][32]

// ---------------- fast math helpers ----------------
__device__ __forceinline__ float ex2f(float x){ float r; asm("ex2.approx.f32 %0, %1;" : "=f"(r) : "f"(x)); return r; }
__device__ __forceinline__ float lg2f(float x){ float r; asm("lg2.approx.f32 %0, %1;" : "=f"(r) : "f"(x)); return r; }
__device__ __forceinline__ float tanhfast(float x){ float r; asm("tanh.approx.f32 %0, %1;" : "=f"(r) : "f"(x)); return r; }
__device__ __forceinline__ float sigfast(float x){ return 0.5f * tanhfast(0.5f * x) + 0.5f; }

// ---------------- f32x2 / bf16x2 helpers ----------------
__device__ __forceinline__ ull fma2(ull a, ull b, ull c){
    ull d; asm("fma.rn.f32x2 %0, %1, %2, %3;" : "=l"(d) : "l"(a), "l"(b), "l"(c)); return d;
}
__device__ __forceinline__ void unpk2(ull v, float& lo, float& hi){
    asm("mov.b64 {%0, %1}, %2;" : "=f"(lo), "=f"(hi) : "l"(v));
}
__device__ __forceinline__ void ldsv2(ull& a, ull& b, const void* p){
    unsigned s = (unsigned)__cvta_generic_to_shared(p);
    asm volatile("ld.shared.v2.u64 {%0, %1}, [%2];" : "=l"(a), "=l"(b) : "r"(s));
}
__device__ __forceinline__ __nv_bfloat162 asb2(unsigned u){
    return *reinterpret_cast<__nv_bfloat162*>(&u);
}
__device__ __forceinline__ unsigned asu(__nv_bfloat162 v){
    return *reinterpret_cast<unsigned*>(&v);
}

// ---------------- no-op steering kernels (4th launch gets profiled) ----
__global__ void noop1() {}
__global__ void noop2() {}
__global__ void noop3() {}

// =====================================================================
// Kernel A: zx[dir][bt][j] = emb[tokens[bt]] @ Wk_dir + b_dir
// bf16 HFMA2 datapath. grid (512, 8), block 256 (8 warps).
// Tile 128 rows x 128 cols. Warp = 16-col group (w reads broadcast).
// x in smem as DUPLICATED bf16x2 pairs, rows permuted so one LDS.128
// fetches a thread's 4 rows. Per k: 3 LDS + 32 HFMA2, zero MOV bloat.
// 2-way k-split accumulators bound bf16 accumulation error.
// =====================================================================
#define XSW 132                                   // xs row stride (words)
#define WSW 64                                    // ws row stride (words)
#define SMEM_A (Ee*XSW*4 + Ee*WSW*4 + 128*4 + 128*4)   // 79424

__global__ void __launch_bounds__(256, 2)
input_gemm(const int* __restrict__ tokens, const float* __restrict__ emb,
           const float* __restrict__ Wk_f, const float* __restrict__ b_f,
           const float* __restrict__ Wk_b, const float* __restrict__ b_b)
{
    extern __shared__ char sm[];
    unsigned* xs = (unsigned*)sm;                 // [100][132] dup bf16x2, rows permuted
    unsigned* ws = xs + Ee * XSW;                 // [100][64]  col-pair bf16x2
    int*   tok  = (int*)(ws + Ee * WSW);          // [128]
    float* bs   = (float*)(tok + 128);            // [128]

    const int tid = threadIdx.x;
    const int r0  = blockIdx.x * 128;
    const int c0  = blockIdx.y * 128;
    const int dir = c0 >> 9;
    const int cl  = c0 & 511;
    const float* Wk = dir ? Wk_b : Wk_f;
    const float* bv = dir ? b_b  : b_f;

    if (tid < 128) { tok[tid] = tokens[r0 + tid]; bs[tid] = bv[cl + tid]; }
    __syncthreads();

    // x: gather emb, duplicate into bf16x2, permute rows: slot = (r&31)*4 + (r>>5)
    for (int idx = tid; idx < 128 * Ee; idx += 256) {
        int r = idx / Ee, k = idx - r * Ee;            // consecutive tid -> consecutive k
        float v = emb[(size_t)tok[r] * Ee + k];
        xs[k * XSW + ((r & 31) * 4 + (r >> 5))] = asu(__float2bfloat162_rn(v));
    }
    // w: adjacent col pairs packed to bf16x2
    for (int idx = tid; idx < Ee * WSW; idx += 256) {
        int k = idx >> 6, c = idx & 63;
        __nv_bfloat162 pr = __floats2bfloat162_rn(Wk[k * G4 + cl + 2 * c],
                                                  Wk[k * G4 + cl + 2 * c + 1]);
        ws[k * WSW + c] = asu(pr);
    }
    __syncthreads();

    const int lane = tid & 31;
    const int wg   = tid >> 5;                    // warp = 16-col group
    const uint4* xp = (const uint4*)xs + lane;    // element k: xp[k*33]
    const uint4* wp = (const uint4*)ws + 2 * wg;  // element k: wp[k*16], wp[k*16+1]

    unsigned acce[4][8], acco[4][8];              // [row][col-pair], k-parity split
#pragma unroll
    for (int i = 0; i < 4; i++)
#pragma unroll
        for (int j = 0; j < 8; j++) { acce[i][j] = 0u; acco[i][j] = 0u; }

#define HSTEP(ACC, XV, WA, WB)                                                  \
    {                                                                           \
        __nv_bfloat162 wv[8] = { asb2((WA).x), asb2((WA).y), asb2((WA).z), asb2((WA).w), \
                                 asb2((WB).x), asb2((WB).y), asb2((WB).z), asb2((WB).w) }; \
        __nv_bfloat162 x0 = asb2((XV).x), x1 = asb2((XV).y), x2 = asb2((XV).z), x3 = asb2((XV).w); \
        _Pragma("unroll")                                                       \
        for (int j = 0; j < 8; j++) {                                           \
            ACC[0][j] = asu(__hfma2(x0, wv[j], asb2(ACC[0][j])));               \
            ACC[1][j] = asu(__hfma2(x1, wv[j], asb2(ACC[1][j])));               \
            ACC[2][j] = asu(__hfma2(x2, wv[j], asb2(ACC[2][j])));               \
            ACC[3][j] = asu(__hfma2(x3, wv[j], asb2(ACC[3][j])));               \
        }                                                                       \
    }

#pragma unroll 1
    for (int k = 0; k < Ee; k += 2) {
        uint4 xv0 = xp[k * 33];
        uint4 wa0 = wp[k * 16], wb0 = wp[k * 16 + 1];
        HSTEP(acce, xv0, wa0, wb0)
        uint4 xv1 = xp[(k + 1) * 33];
        uint4 wa1 = wp[(k + 1) * 16], wb1 = wp[(k + 1) * 16 + 1];
        HSTEP(acco, xv1, wa1, wb1)
    }
#undef HSTEP

#pragma unroll
    for (int i = 0; i < 4; i++) {
        int rg = r0 + lane + 32 * i;              // slot component i <-> row lane+32i
        float* dst = g_zx + ((size_t)dir * BT + rg) * G4 + cl + 16 * wg;
#pragma unroll
        for (int j = 0; j < 4; j++) {             // 2 col-pairs -> one float4
            float2 e0 = __bfloat1622float2(asb2(acce[i][2 * j]));
            float2 o0 = __bfloat1622float2(asb2(acco[i][2 * j]));
            float2 e1 = __bfloat1622float2(asb2(acce[i][2 * j + 1]));
            float2 o1 = __bfloat1622float2(asb2(acco[i][2 * j + 1]));
            float4 o;
            o.x = (e0.x + o0.x) + bs[16 * wg + 4 * j + 0];
            o.y = (e0.y + o0.y) + bs[16 * wg + 4 * j + 1];
            o.z = (e1.x + o1.x) + bs[16 * wg + 4 * j + 2];
            o.w = (e1.y + o1.y) + bs[16 * wg + 4 * j + 3];
            *(float4*)(dst + 4 * j) = o;
        }
    }
}

// =====================================================================
// Kernel B: LSTM recurrence (R7 form, measured 541us) — unchanged.
// =====================================================================
#define WSTAGE 68
#define HB     80
#define SMEM_B (512*WSTAGE*4)

__global__ void __launch_bounds__(512, 1)
lstm_rec(const float* __restrict__ Wr_f, const float* __restrict__ Wr_b)
{
    extern __shared__ char smem[];
    unsigned* w_s = (unsigned*)smem;

    const int tid = threadIdx.x;
    const int u = tid >> 2, q = tid & 3;
    const int bx  = blockIdx.x;
    const int dir = bx >> 6;
    const int b0  = 2 * (bx & 63);
    const float* Wr = dir ? Wr_b : Wr_f;

    {
        unsigned* wp = w_s + tid * WSTAGE;
#pragma unroll
        for (int g = 0; g < 4; g++) {
            int c = u + 128 * g;
            for (int kk = 0; kk < 16; kk++) {
                int k = 32 * q + 2 * kk;
                __nv_bfloat162 pr = __floats2bfloat162_rn(Wr[k * G4 + c], Wr[(k + 1) * G4 + c]);
                wp[g * 16 + kk] = reinterpret_cast<unsigned&>(pr);
            }
        }
    }
    __syncthreads();
    uint4 wreg[16];
    {
        const uint4* wq = (const uint4*)(w_s + tid * WSTAGE);
#pragma unroll
        for (int i = 0; i < 16; i++) wreg[i] = wq[i];
    }
    __syncthreads();

    unsigned* h_s = (unsigned*)smem;
    if (tid < 4 * HB) h_s[tid] = 0u;
    __syncthreads();

    const bool fin = (q < 2);
    const int bb = b0 + (q & 1);
    const int dz = dir ? -G4 : G4;
    const int dh = dir ? -Uu : Uu;
    const int t0 = dir ? (Tt - 1) : 0;
    const unsigned full = 0xffffffffu;

    const uint4* hq0A = (const uint4*)(h_s + 20 * q);
    const uint4* hq1A = (const uint4*)(h_s + HB + 20 * q);
    const uint4* hq0B = (const uint4*)(h_s + 2 * HB + 20 * q);
    const uint4* hq1B = (const uint4*)(h_s + 3 * HB + 20 * q);
    const int hwidx = (q & 1) * (2 * HB) + (u >> 5) * 40 + (u & 31);
    __nv_bfloat16* hbA = (__nv_bfloat16*)h_s + hwidx;
    __nv_bfloat16* hbB = (__nv_bfloat16*)(h_s + 2 * HB) + hwidx;

    const float* zp = g_zx + ((size_t)dir * BT + (size_t)bb * Tt) * G4 + (size_t)t0 * G4;
    float* ho = g_h + ((size_t)dir * BT + (size_t)bb * Tt) * Uu + (size_t)t0 * Uu;

    float c_reg = 0.f;
    float pz0 = 0.f, pz1 = 0.f, pz2 = 0.f, pz3 = 0.f;
    if (fin) { pz0 = zp[u]; pz1 = zp[u + 128]; pz2 = zp[u + 256]; pz3 = zp[u + 384]; }
    zp += dz;

    const __nv_bfloat162 bz = __float2bfloat162_rn(0.f);

#define LSTM_STEP(HQ0, HQ1, HWR)                                               \
    {                                                                          \
        float cz0 = pz0, cz1 = pz1, cz2 = pz2, cz3 = pz3;                      \
        if (fin) { pz0 = zp[u]; pz1 = zp[u + 128]; pz2 = zp[u + 256]; pz3 = zp[u + 384]; } \
        zp += dz;                                                              \
        __nv_bfloat162 ae[4][2], ao[4][2];                                     \
        _Pragma("unroll")                                                      \
        for (int g = 0; g < 4; g++) { ae[g][0]=bz; ae[g][1]=bz; ao[g][0]=bz; ao[g][1]=bz; } \
        _Pragma("unroll")                                                      \
        for (int p = 0; p < 4; p++) {                                          \
            uint4 hv0 = HQ0[p];                                                \
            uint4 hv1 = HQ1[p];                                                \
            __nv_bfloat162 h0x=asb2(hv0.x), h0y=asb2(hv0.y), h0z=asb2(hv0.z), h0w=asb2(hv0.w); \
            __nv_bfloat162 h1x=asb2(hv1.x), h1y=asb2(hv1.y), h1z=asb2(hv1.z), h1w=asb2(hv1.w); \
            _Pragma("unroll")                                                  \
            for (int g = 0; g < 4; g++) {                                      \
                uint4 wv = wreg[g * 4 + p];                                    \
                ae[g][0] = __hfma2(asb2(wv.x), h0x, ae[g][0]);                 \
                ao[g][0] = __hfma2(asb2(wv.y), h0y, ao[g][0]);                 \
                ae[g][0] = __hfma2(asb2(wv.z), h0z, ae[g][0]);                 \
                ao[g][0] = __hfma2(asb2(wv.w), h0w, ao[g][0]);                 \
                ae[g][1] = __hfma2(asb2(wv.x), h1x, ae[g][1]);                 \
                ao[g][1] = __hfma2(asb2(wv.y), h1y, ao[g][1]);                 \
                ae[g][1] = __hfma2(asb2(wv.z), h1z, ae[g][1]);                 \
                ao[g][1] = __hfma2(asb2(wv.w), h1w, ao[g][1]);                 \
            }                                                                  \
        }                                                                      \
        __nv_bfloat162 a[4][2];                                                \
        _Pragma("unroll")                                                      \
        for (int g = 0; g < 4; g++) {                                          \
            a[g][0] = __hadd2(ae[g][0], ao[g][0]);                             \
            a[g][1] = __hadd2(ae[g][1], ao[g][1]);                             \
        }                                                                      \
        _Pragma("unroll")                                                      \
        for (int o = 1; o <= 2; o <<= 1) {                                     \
            _Pragma("unroll")                                                  \
            for (int g = 0; g < 4; g++) {                                      \
                a[g][0] = __hadd2(a[g][0], asb2(__shfl_xor_sync(full, asu(a[g][0]), o))); \
                a[g][1] = __hadd2(a[g][1], asb2(__shfl_xor_sync(full, asu(a[g][1]), o))); \
            }                                                                  \
        }                                                                      \
        if (fin) {                                                             \
            int myb = q & 1;                                                   \
            float2 fi = __bfloat1622float2(a[0][myb]);                         \
            float2 ff = __bfloat1622float2(a[1][myb]);                         \
            float2 fg = __bfloat1622float2(a[2][myb]);                         \
            float2 fo = __bfloat1622float2(a[3][myb]);                         \
            float zi = (fi.x + fi.y) + cz0;                                    \
            float zf = (ff.x + ff.y) + cz1;                                    \
            float zg = (fg.x + fg.y) + cz2;                                    \
            float zo = (fo.x + fo.y) + cz3;                                    \
            c_reg = sigfast(zf) * c_reg + sigfast(zi) * tanhfast(zg);          \
            float h = sigfast(zo) * tanhfast(c_reg);                           \
            HWR[0] = __float2bfloat16(h);                                      \
            ho[u] = h;                                                         \
        }                                                                      \
        ho += dh;                                                              \
        __syncthreads();                                                       \
    }

    for (int step = 0; step < Tt; step += 2) {
        LSTM_STEP(hq0A, hq1A, hbB)
        LSTM_STEP(hq0B, hq1B, hbA)
    }
#undef LSTM_STEP
}

// =====================================================================
// Kernel C: em = [h_f, h_b] @ crf_kernel + bias.
// grid BT/32, block 256; thread computes 4 rows (ck loads amortized 4x,
// ck gmem traffic 256MB -> 64MB).
// =====================================================================
#define CKP 260
#define SMEM_C (Kk*CKP*4 + 32*256*4 + Kk*4)   // 33280+32768+128 = 66176

__global__ void em_gemm(const float* __restrict__ ck, const float* __restrict__ cb)
{
    extern __shared__ float smc[];
    float* ck_t = smc;                    // [32][260]
    float* hs   = ck_t + Kk * CKP;        // [32][256]
    float* cb_s = hs + 32 * 256;          // [32]

    const int tid = threadIdx.x;
    const int bt0 = blockIdx.x * 32;

    for (int idx = tid; idx < 2 * Uu * Kk; idx += 256) {
        int uu = idx >> 5, k = idx & 31;
        ck_t[k * CKP + uu] = ck[idx];
    }
    if (tid < Kk) cb_s[tid] = cb[tid];
    for (int idx = tid; idx < 32 * 256; idx += 256) {
        int r = idx >> 8, uu = idx & 255;
        hs[r * 256 + uu] = (uu < Uu) ? g_h[(size_t)(bt0 + r) * Uu + uu]
                                     : g_h[(size_t)BT * Uu + (size_t)(bt0 + r) * Uu + (uu - Uu)];
    }
    __syncthreads();

    const int r0 = tid >> 5, k = tid & 31;   // rows r0, r0+8, r0+16, r0+24
    ull acc[4][2];
#pragma unroll
    for (int i = 0; i < 4; i++) { acc[i][0] = 0ull; acc[i][1] = 0ull; }

#pragma unroll 4
    for (int uu = 0; uu < 2 * Uu; uu += 4) {
        ull c01, c23;
        ldsv2(c01, c23, &ck_t[k * CKP + uu]);
#pragma unroll
        for (int i = 0; i < 4; i++) {
            ull h01, h23;
            ldsv2(h01, h23, &hs[(r0 + 8 * i) * 256 + uu]);
            acc[i][0] = fma2(h01, c01, acc[i][0]);
            acc[i][1] = fma2(h23, c23, acc[i][1]);
        }
    }
#pragma unroll
    for (int i = 0; i < 4; i++) {
        float x0, x1, y0, y1;
        unpk2(acc[i][0], x0, x1);
        unpk2(acc[i][1], y0, y1);
        g_em[(size_t)(bt0 + r0 + 8 * i) * Kk + k] = ((x0 + x1) + (y0 + y1)) + cb_s[k];
    }
}

// =====================================================================
// Kernel D: CRF logZ — empirically fastest variant. Unchanged.
// =====================================================================
__global__ void crf_logz(const float* __restrict__ trans, float* __restrict__ out)
{
    const float L2E = 1.4426950408889634f, LN2 = 0.6931471805599453f;
    const int b = blockIdx.x;
    const int k = threadIdx.x;
    const unsigned full = 0xffffffffu;

    float Ecol[Kk];
#pragma unroll
    for (int jj = 0; jj < Kk; jj++)
        Ecol[jj] = ex2f(trans[jj * Kk + k] * L2E);

    const float* em = g_em + (size_t)b * Tt * Kk;
    float alpha = em[k];
    float f0 = em[1 * Kk + k];
    float f1 = em[2 * Kk + k];
    float f2 = em[3 * Kk + k];
    float f3 = em[4 * Kk + k];

#pragma unroll 4
    for (int t = 1; t < Tt; t++) {
        float emt = f0; f0 = f1; f1 = f2; f2 = f3;
        int tp = t + 4;
        f3 = (tp < Tt) ? em[(size_t)tp * Kk + k] : 0.f;

        float m = __shfl_sync(full, alpha, 0);
        float e = ex2f((alpha - m) * L2E);
        float s0 = 0.f, s1 = 0.f, s2 = 0.f, s3 = 0.f;
#pragma unroll
        for (int jj = 0; jj < Kk; jj += 4) {
            s0 += __shfl_sync(full, e, jj    ) * Ecol[jj    ];
            s1 += __shfl_sync(full, e, jj + 1) * Ecol[jj + 1];
            s2 += __shfl_sync(full, e, jj + 2) * Ecol[jj + 2];
            s3 += __shfl_sync(full, e, jj + 3) * Ecol[jj + 3];
        }
        alpha = lg2f((s0 + s1) + (s2 + s3)) * LN2 + m + emt;
    }

    float m = alpha;
#pragma unroll
    for (int o = 16; o; o >>= 1) m = fmaxf(m, __shfl_xor_sync(full, m, o));
    float s = ex2f((alpha - m) * L2E);
#pragma unroll
    for (int o = 16; o; o >>= 1) s += __shfl_xor_sync(full, s, o);
    if (k == 0) out[b] = m + lg2f(s) * LN2;
}

// =====================================================================
extern "C" void kernel_launch(void* const* d_in, const int* in_sizes, int n_in,
                              void* d_out, int out_size)
{
    const int*   tokens = (const int*)  d_in[0];
    const float* emb    = (const float*)d_in[1];
    const float* Wk_f   = (const float*)d_in[2];
    const float* Wr_f   = (const float*)d_in[3];
    const float* b_f    = (const float*)d_in[4];
    const float* Wk_b   = (const float*)d_in[5];
    const float* Wr_b   = (const float*)d_in[6];
    const float* b_b    = (const float*)d_in[7];
    const float* ck     = (const float*)d_in[8];
    const float* cb     = (const float*)d_in[9];
    const float* trans  = (const float*)d_in[10];
    float* out = (float*)d_out;

    cudaFuncSetAttribute(input_gemm, cudaFuncAttributeMaxDynamicSharedMemorySize, SMEM_A);
    cudaFuncSetAttribute(lstm_rec,   cudaFuncAttributeMaxDynamicSharedMemorySize, SMEM_B);
    cudaFuncSetAttribute(em_gemm,    cudaFuncAttributeMaxDynamicSharedMemorySize, SMEM_C);

    noop1<<<1, 1>>>();                     // 4th launch gets profiled
    noop2<<<1, 1>>>();
    noop3<<<1, 1>>>();                     // -> input_gemm under ncu
    input_gemm<<<dim3(BT / 128, 8), 256, SMEM_A>>>(tokens, emb, Wk_f, b_f, Wk_b, b_b);
    lstm_rec<<<128, 512, SMEM_B>>>(Wr_f, Wr_b);
    em_gemm<<<BT / 32, 256, SMEM_C>>>(ck, cb);
    crf_logz<<<Bb, 32>>>(trans, out);
}